// round 1
// baseline (speedup 1.0000x reference)
#include <cuda_runtime.h>
#include <math_constants.h>

#define N_TOK 131072
#define IN_F  128
#define OUT_F 256
#define LAT_F 128
#define NEXP  8
#define OMEGA 30.0f

#define TM 128
#define TN 64
#define KC 16
#define TH 256

// ---------------- scratch (static __device__, no allocations) ----------------
__device__ int   g_count[NEXP];
__device__ int   g_tok[NEXP * N_TOK];     // (slot<<24) | token
__device__ float g_wt [NEXP * N_TOK];
__device__ float g_part[2][N_TOK][OUT_F]; // 256 MB partial contributions

// ---------------- helpers ----------------
__device__ __forceinline__ float sin_red(float xx) {
    // range-reduce to [-pi, pi] so accuracy is robust regardless of fast-math
    float k = rintf(xx * 0.15915494309189535f);
    float r = fmaf(k, -6.2831854820251465f, xx);   // x - k*2pi_hi
    r = fmaf(k, 1.7484556e-07f, r);                // - k*2pi_lo (lo is negative)
    return sinf(r);
}

// ---------------- kernel 0: zero counters ----------------
__global__ void init_kernel() {
    if (threadIdx.x < NEXP) g_count[threadIdx.x] = 0;
}

// ---------------- kernel 1: gating + routing ----------------
__global__ void gate_kernel(const float* __restrict__ x,
                            const float* __restrict__ gw,
                            const float* __restrict__ gb) {
    __shared__ float s_gw[IN_F * NEXP];
    __shared__ float s_gb[NEXP];
    int tid = threadIdx.x;
    for (int i = tid; i < IN_F * NEXP; i += blockDim.x) s_gw[i] = gw[i];
    if (tid < NEXP) s_gb[tid] = gb[tid];
    __syncthreads();

    int warp = tid >> 5, lane = tid & 31;
    int t = blockIdx.x * 8 + warp;

    float4 xv = *(const float4*)(x + (size_t)t * IN_F + lane * 4);
    int k0 = lane * 4;
    float p[NEXP];
#pragma unroll
    for (int e = 0; e < NEXP; e++) {
        float acc = xv.x * s_gw[(k0 + 0) * NEXP + e];
        acc = fmaf(xv.y, s_gw[(k0 + 1) * NEXP + e], acc);
        acc = fmaf(xv.z, s_gw[(k0 + 2) * NEXP + e], acc);
        acc = fmaf(xv.w, s_gw[(k0 + 3) * NEXP + e], acc);
        p[e] = acc;
    }
#pragma unroll
    for (int off = 16; off; off >>= 1)
#pragma unroll
        for (int e = 0; e < NEXP; e++)
            p[e] += __shfl_xor_sync(0xffffffffu, p[e], off);

    if (lane == 0) {
        float best = -CUDART_INF_F, sec = -CUDART_INF_F;
        int bi = 0, si = 0;
#pragma unroll
        for (int e = 0; e < NEXP; e++) {
            float v = p[e] + s_gb[e];
            if (v > best) { sec = best; si = bi; best = v; bi = e; }
            else if (v > sec) { sec = v; si = e; }
        }
        float w0 = 1.0f / (1.0f + expf(sec - best));
        float w1 = 1.0f - w0;
        int p0 = atomicAdd(&g_count[bi], 1);
        g_tok[bi * N_TOK + p0] = t;              // slot 0
        g_wt [bi * N_TOK + p0] = w0;
        int p1 = atomicAdd(&g_count[si], 1);
        g_tok[si * N_TOK + p1] = t | (1 << 24);  // slot 1
        g_wt [si * N_TOK + p1] = w1;
    }
}

// ---------------- kernel 2: grouped expert GEMM + fused sin epilogue ----------------
// Block: TM=128 tokens x TN=64 cols, 3 accumulation planes (h, scale, shift).
// Thread layout: tm = tid&15 (token groups, strided by 16), tn = tid>>4 (col quads).
__global__ __launch_bounds__(TH) void expert_kernel(
    const float* __restrict__ x,  const float* __restrict__ lat,
    const float* __restrict__ W,  const float* __restrict__ b,
    const float* __restrict__ Wl, const float* __restrict__ bl)
{
    __shared__ float xs[TM][KC + 1];
    __shared__ float ls[TM][KC + 1];
    __shared__ float ws [KC][TN + 4];
    __shared__ float wl0[KC][TN + 4];
    __shared__ float wl1[KC][TN + 4];
    __shared__ int   s_tok[TM];
    __shared__ int   s_slot[TM];
    __shared__ float s_wt[TM];

    int e = blockIdx.z;
    int cnt = g_count[e];
    int m0 = blockIdx.x * TM;
    if (m0 >= cnt) return;
    int rows = min(TM, cnt - m0);
    int n0 = blockIdx.y * TN;
    int tid = threadIdx.x;

    if (tid < TM) {
        int entry = (tid < rows) ? g_tok[e * N_TOK + m0 + tid] : 0;
        s_tok [tid] = entry & 0xFFFFFF;
        s_slot[tid] = entry >> 24;
        s_wt  [tid] = (tid < rows) ? g_wt[e * N_TOK + m0 + tid] : 0.0f;
    }
    __syncthreads();

    float acc_h[8][4] = {}, acc_s[8][4] = {}, acc_t[8][4] = {};
    int tm = tid & 15, tn = tid >> 4;

    const float* We  = W  + (size_t)e * IN_F  * OUT_F;
    const float* Wle = Wl + (size_t)e * LAT_F * (2 * OUT_F);

    for (int kc = 0; kc < IN_F; kc += KC) {
        // ---- load A tiles (gathered rows): 128 rows x 16 floats, 2 float4 per thread
#pragma unroll
        for (int i = 0; i < 2; i++) {
            int idx = tid + TH * i;
            int m = idx >> 2, q = (idx & 3) * 4;
            int t = s_tok[m];
            float4 v = *(const float4*)(x   + (size_t)t * IN_F  + kc + q);
            xs[m][q + 0] = v.x; xs[m][q + 1] = v.y; xs[m][q + 2] = v.z; xs[m][q + 3] = v.w;
            float4 u = *(const float4*)(lat + (size_t)t * LAT_F + kc + q);
            ls[m][q + 0] = u.x; ls[m][q + 1] = u.y; ls[m][q + 2] = u.z; ls[m][q + 3] = u.w;
        }
        // ---- load B tiles: 16 x 64 each, 1 float4 per thread per matrix
        {
            int kk = tid >> 4, nq = (tid & 15) * 4;
            *(float4*)&ws [kk][nq] = *(const float4*)(We  + (size_t)(kc + kk) * OUT_F       + n0 + nq);
            *(float4*)&wl0[kk][nq] = *(const float4*)(Wle + (size_t)(kc + kk) * (2 * OUT_F) + n0 + nq);
            *(float4*)&wl1[kk][nq] = *(const float4*)(Wle + (size_t)(kc + kk) * (2 * OUT_F) + n0 + nq + OUT_F);
        }
        __syncthreads();

#pragma unroll
        for (int kk = 0; kk < KC; kk++) {
            float a[8], al[8];
#pragma unroll
            for (int i = 0; i < 8; i++) {
                a [i] = xs[tm + 16 * i][kk];
                al[i] = ls[tm + 16 * i][kk];
            }
            float4 bw = *(const float4*)&ws [kk][tn * 4];
            float4 b0 = *(const float4*)&wl0[kk][tn * 4];
            float4 b1 = *(const float4*)&wl1[kk][tn * 4];
            float bwv[4] = {bw.x, bw.y, bw.z, bw.w};
            float b0v[4] = {b0.x, b0.y, b0.z, b0.w};
            float b1v[4] = {b1.x, b1.y, b1.z, b1.w};
#pragma unroll
            for (int i = 0; i < 8; i++)
#pragma unroll
                for (int j = 0; j < 4; j++) {
                    acc_h[i][j] = fmaf(a [i], bwv[j], acc_h[i][j]);
                    acc_s[i][j] = fmaf(al[i], b0v[j], acc_s[i][j]);
                    acc_t[i][j] = fmaf(al[i], b1v[j], acc_t[i][j]);
                }
        }
        __syncthreads();
    }

    // ---- fused epilogue: biases, sin, gate weight, float4 store into partials
    float bb[4], bs[4], bt[4];
#pragma unroll
    for (int j = 0; j < 4; j++) {
        int c = n0 + tn * 4 + j;
        bb[j] = b [e * OUT_F + c];
        bs[j] = bl[e * (2 * OUT_F) + c];
        bt[j] = bl[e * (2 * OUT_F) + OUT_F + c];
    }
#pragma unroll
    for (int i = 0; i < 8; i++) {
        int m = tm + 16 * i;
        if (m < rows) {
            int t = s_tok[m], sl = s_slot[m];
            float w = s_wt[m];
            float4 o;
            float ov[4];
#pragma unroll
            for (int j = 0; j < 4; j++) {
                float h  = acc_h[i][j] + bb[j];
                float sc = acc_s[i][j] + bs[j];
                float sh = acc_t[i][j] + bt[j];
                float arg = fmaf(OMEGA * h, sc, sh);
                ov[j] = w * sin_red(arg);
            }
            o.x = ov[0]; o.y = ov[1]; o.z = ov[2]; o.w = ov[3];
            *(float4*)&g_part[sl][t][n0 + tn * 4] = o;
        }
    }
}

// ---------------- kernel 3: combine the two slot contributions ----------------
__global__ void combine_kernel(float* __restrict__ out) {
    size_t i = (size_t)blockIdx.x * blockDim.x + threadIdx.x;
    const float4* p0 = (const float4*)&g_part[0][0][0];
    const float4* p1 = (const float4*)&g_part[1][0][0];
    float4 a = p0[i], c = p1[i];
    float4 r = make_float4(a.x + c.x, a.y + c.y, a.z + c.z, a.w + c.w);
    ((float4*)out)[i] = r;
}

// ---------------- launch ----------------
extern "C" void kernel_launch(void* const* d_in, const int* in_sizes, int n_in,
                              void* d_out, int out_size) {
    const float* x   = (const float*)d_in[0];
    const float* lat = (const float*)d_in[1];
    const float* gw  = (const float*)d_in[2];
    const float* gb  = (const float*)d_in[3];
    const float* W   = (const float*)d_in[4];
    const float* b   = (const float*)d_in[5];
    const float* Wl  = (const float*)d_in[6];
    const float* bl  = (const float*)d_in[7];
    float* out = (float*)d_out;

    init_kernel<<<1, 32>>>();
    gate_kernel<<<N_TOK / 8, 256>>>(x, gw, gb);
    // latents passthrough -> tail of output
    cudaMemcpyAsync(out + (size_t)N_TOK * OUT_F, lat,
                    (size_t)N_TOK * LAT_F * sizeof(float),
                    cudaMemcpyDeviceToDevice);
    expert_kernel<<<dim3(N_TOK / TM, OUT_F / TN, NEXP), TH>>>(x, lat, W, b, Wl, bl);
    combine_kernel<<<(N_TOK * OUT_F / 4) / 256, 256>>>(out);
}

// round 3
// speedup vs baseline: 2.4377x; 2.4377x over previous
#include <cuda_runtime.h>
#include <cuda_fp16.h>
#include <math_constants.h>
#include <cstdint>

#define N_TOK 131072
#define IN_F  128
#define OUT_F 256
#define NEXP  8
#define OMEGA 30.0f

#define TM 128
#define TH 256

#define SA 136              // A smem row stride (halves), 128 + 8 pad
#define SB 72               // B smem row stride (halves), 64 + 8 pad
#define A_TILE_B 34816      // 128*136*2 bytes
#define B_BASE_B 139264     // 4 * A_TILE_B
#define B_TILE_B 9216       // 64*72*2 bytes
#define SMEM_BYTES (B_BASE_B + 6 * B_TILE_B)   // 194560

// ---------------- scratch ----------------
__device__ int   g_count[NEXP];
__device__ int   g_tok[NEXP * N_TOK];     // (slot<<24) | token
__device__ float g_wt [NEXP * N_TOK];
__device__ float g_part[2][N_TOK][OUT_F];

// ---------------- PTX helpers (all compute_80-portable) ----------------
__device__ __forceinline__ uint32_t smem_u32(const void* p) {
    uint32_t a;
    asm("{ .reg .u64 t; cvta.to.shared.u64 t, %1; cvt.u32.u64 %0, t; }" : "=r"(a) : "l"(p));
    return a;
}
__device__ __forceinline__ void ldsm_x4(uint32_t* r, uint32_t addr) {
    asm volatile("ldmatrix.sync.aligned.m8n8.x4.shared.b16 {%0,%1,%2,%3}, [%4];"
        : "=r"(r[0]), "=r"(r[1]), "=r"(r[2]), "=r"(r[3]) : "r"(addr));
}
__device__ __forceinline__ void ldsm_x4t(uint32_t* r, uint32_t addr) {
    asm volatile("ldmatrix.sync.aligned.m8n8.x4.trans.shared.b16 {%0,%1,%2,%3}, [%4];"
        : "=r"(r[0]), "=r"(r[1]), "=r"(r[2]), "=r"(r[3]) : "r"(addr));
}
__device__ __forceinline__ void mma_f16(float (&c)[4], const uint32_t (&a)[4],
                                        const uint32_t* b) {
    asm volatile("mma.sync.aligned.m16n8k16.row.col.f32.f16.f16.f32 "
        "{%0,%1,%2,%3}, {%4,%5,%6,%7}, {%8,%9}, {%0,%1,%2,%3};"
        : "+f"(c[0]), "+f"(c[1]), "+f"(c[2]), "+f"(c[3])
        : "r"(a[0]), "r"(a[1]), "r"(a[2]), "r"(a[3]), "r"(b[0]), "r"(b[1]));
}
// split one float pair into packed fp16 hi and fp16 lo (residual)
__device__ __forceinline__ void split2(float a, float b, uint32_t& hi, uint32_t& lo) {
    __half2 h = __floats2half2_rn(a, b);
    float2 hf = __half22float2(h);
    __half2 l = __floats2half2_rn(a - hf.x, b - hf.y);
    hi = *(uint32_t*)&h;
    lo = *(uint32_t*)&l;
}

// ---------------- fast sin: pi-reduction + degree-11 odd poly ----------------
__device__ __forceinline__ float fast_sin(float x) {
    float q = rintf(x * 0.3183098861837907f);
    int qi = (int)q;
    float r = fmaf(q, -3.14159274101257324f, x);
    r = fmaf(q, 8.74227765734758577e-8f, r);
    float z = r * r;
    float p = fmaf(z, -2.50521084e-8f, 2.75573192e-6f);
    p = fmaf(z, p, -1.98412698e-4f);
    p = fmaf(z, p, 8.33333333e-3f);
    p = fmaf(z, p, -1.66666667e-1f);
    float s = fmaf(r * z, p, r);
    return __int_as_float(__float_as_int(s) ^ ((qi & 1) << 31));
}

// ---------------- kernel 0: zero counters ----------------
__global__ void init_kernel() {
    if (threadIdx.x < NEXP) g_count[threadIdx.x] = 0;
}

// ---------------- kernel 1: gating + routing ----------------
__global__ void gate_kernel(const float* __restrict__ x,
                            const float* __restrict__ gw,
                            const float* __restrict__ gb) {
    __shared__ float s_gw[IN_F * NEXP];
    __shared__ float s_gb[NEXP];
    int tid = threadIdx.x;
    for (int i = tid; i < IN_F * NEXP; i += blockDim.x) s_gw[i] = gw[i];
    if (tid < NEXP) s_gb[tid] = gb[tid];
    __syncthreads();

    int warp = tid >> 5, lane = tid & 31;
    int t = blockIdx.x * 8 + warp;

    float4 xv = *(const float4*)(x + (size_t)t * IN_F + lane * 4);
    int k0 = lane * 4;
    float p[NEXP];
#pragma unroll
    for (int e = 0; e < NEXP; e++) {
        float acc = xv.x * s_gw[(k0 + 0) * NEXP + e];
        acc = fmaf(xv.y, s_gw[(k0 + 1) * NEXP + e], acc);
        acc = fmaf(xv.z, s_gw[(k0 + 2) * NEXP + e], acc);
        acc = fmaf(xv.w, s_gw[(k0 + 3) * NEXP + e], acc);
        p[e] = acc;
    }
#pragma unroll
    for (int off = 16; off; off >>= 1)
#pragma unroll
        for (int e = 0; e < NEXP; e++)
            p[e] += __shfl_xor_sync(0xffffffffu, p[e], off);

    if (lane == 0) {
        float best = -CUDART_INF_F, sec = -CUDART_INF_F;
        int bi = 0, si = 0;
#pragma unroll
        for (int e = 0; e < NEXP; e++) {
            float v = p[e] + s_gb[e];
            if (v > best) { sec = best; si = bi; best = v; bi = e; }
            else if (v > sec) { sec = v; si = e; }
        }
        float w0 = 1.0f / (1.0f + expf(sec - best));
        float w1 = 1.0f - w0;
        int p0 = atomicAdd(&g_count[bi], 1);
        g_tok[bi * N_TOK + p0] = t;
        g_wt [bi * N_TOK + p0] = w0;
        int p1 = atomicAdd(&g_count[si], 1);
        g_tok[si * N_TOK + p1] = t | (1 << 24);
        g_wt [si * N_TOK + p1] = w1;
    }
}

// ---------------- kernel 2: split-fp16 mma.sync grouped GEMM + fused sin ----------------
// A tiles (smem, halves): 0=x_hi 1=x_lo 2=lat_hi 3=lat_lo, [128][136]
// B tiles per 64-col ctile, staged in K-chunks of 64: [64][72], order d0h d0l d1h d1l d2h d2l
__global__ __launch_bounds__(TH) void expert_kernel(
    const float* __restrict__ x,  const float* __restrict__ lat,
    const float* __restrict__ W,  const float* __restrict__ b,
    const float* __restrict__ Wl, const float* __restrict__ bl)
{
    extern __shared__ __align__(16) __half sm[];
    __shared__ int   s_ent[TM];
    __shared__ float s_w[TM];

    int e = blockIdx.y;
    int cnt = g_count[e];
    int m0 = blockIdx.x * TM;
    if (m0 >= cnt) return;
    int rows = min(TM, cnt - m0);
    int tid = threadIdx.x;
    int w = tid >> 5, lane = tid & 31;

    if (tid < TM) {
        int ent = (tid < rows) ? g_tok[e * N_TOK + m0 + tid] : 0;
        s_ent[tid] = ent;
        s_w[tid]   = (tid < rows) ? g_wt[e * N_TOK + m0 + tid] : 0.0f;
    }
    __syncthreads();

    // ---- stage A: gather x/lat rows, split into fp16 hi/lo
#pragma unroll
    for (int s2 = 0; s2 < 2; s2++) {
        const float* src = s2 ? lat : x;
        __half* hiT = sm + (size_t)(s2 * 2) * (128 * SA);
#pragma unroll
        for (int it = 0; it < 16; it++) {
            int idx = it * TH + tid;         // 0..4095
            int m = idx >> 5, k = (idx & 31) * 4;
            int tok = s_ent[m] & 0xFFFFFF;
            float4 v = *(const float4*)(src + (size_t)tok * IN_F + k);
            uint32_t h01, l01, h23, l23;
            split2(v.x, v.y, h01, l01);
            split2(v.z, v.w, h23, l23);
            __half* p = hiT + m * SA + k;
            uint2 uh; uh.x = h01; uh.y = h23;
            uint2 ul; ul.x = l01; ul.y = l23;
            *(uint2*)p = uh;
            *(uint2*)(p + 128 * SA) = ul;
        }
    }

    const float* We  = W  + (size_t)e * IN_F * OUT_F;
    const float* Wle = Wl + (size_t)e * IN_F * (2 * OUT_F);

    uint32_t smu = smem_u32(sm);
    int wm = w >> 1, wn = w & 1;
    // A ldmatrix lane offsets (bytes): frag f covers rows wm*32+f*16+[0,16)
    uint32_t aoff0 = (uint32_t)(((wm * 32 + (lane & 15)) * SA + (lane >> 4) * 8) * 2);
    uint32_t aoff1 = aoff0 + 16 * SA * 2;
    // B ldmatrix.trans lane offset (bytes) within a chunk tile
    uint32_t bcon = (uint32_t)((((lane & 7) + ((lane >> 3) & 1) * 8) * SB
                               + ((lane >> 4) & 1) * 8 + wn * 32) * 2);

    for (int ct = 0; ct < 4; ct++) {
        int n0c = ct * 64;
        float acc[3][2][4][4];
#pragma unroll
        for (int d = 0; d < 3; d++)
#pragma unroll
            for (int mf = 0; mf < 2; mf++)
#pragma unroll
                for (int nf = 0; nf < 4; nf++)
#pragma unroll
                    for (int q = 0; q < 4; q++) acc[d][mf][nf][q] = 0.0f;

#pragma unroll
        for (int kc = 0; kc < IN_F; kc += 64) {
            __syncthreads();   // previous chunk consumers done
            // ---- stage B chunk: 3 outputs x hi/lo, [64][72]
#pragma unroll
            for (int d = 0; d < 3; d++) {
                const float* src = (d == 0) ? (We + n0c)
                                 : (Wle + n0c + (d == 2 ? OUT_F : 0));
                int ldm = (d == 0) ? OUT_F : 2 * OUT_F;
                __half* bt = sm + (B_BASE_B / 2) + (size_t)(d * 2) * (64 * SB);
#pragma unroll
                for (int it = 0; it < 4; it++) {
                    int idx = it * TH + tid;   // 0..1023
                    int kl = idx >> 4, q = (idx & 15) * 4;
                    float4 v = *(const float4*)(src + (size_t)(kc + kl) * ldm + q);
                    uint32_t h01, l01, h23, l23;
                    split2(v.x, v.y, h01, l01);
                    split2(v.z, v.w, h23, l23);
                    __half* p = bt + kl * SB + q;
                    uint2 uh; uh.x = h01; uh.y = h23;
                    uint2 ul; ul.x = l01; ul.y = l23;
                    *(uint2*)p = uh;
                    *(uint2*)(p + 64 * SB) = ul;
                }
            }
            __syncthreads();

            // ---- 4 k16 steps
#pragma unroll
            for (int kk = 0; kk < 4; kk++) {
                uint32_t kby = (uint32_t)(kc + kk * 16) * 2;
                uint32_t kbb = (uint32_t)(kk * 16 * SB) * 2;
                uint32_t AH[2][4], AL[2][4];
                uint32_t bh[8], blo[8];

                // x fragments -> output d0
                ldsm_x4(AH[0], smu + aoff0 + kby);
                ldsm_x4(AH[1], smu + aoff1 + kby);
                ldsm_x4(AL[0], smu + A_TILE_B + aoff0 + kby);
                ldsm_x4(AL[1], smu + A_TILE_B + aoff1 + kby);
                {
                    uint32_t bb = smu + B_BASE_B;
                    ldsm_x4t(&bh[0],  bb + bcon + kbb);
                    ldsm_x4t(&bh[4],  bb + bcon + kbb + 32);
                    ldsm_x4t(&blo[0], bb + B_TILE_B + bcon + kbb);
                    ldsm_x4t(&blo[4], bb + B_TILE_B + bcon + kbb + 32);
#pragma unroll
                    for (int mf = 0; mf < 2; mf++)
#pragma unroll
                        for (int nf = 0; nf < 4; nf++) {
                            mma_f16(acc[0][mf][nf], AH[mf], &bh[nf * 2]);
                            mma_f16(acc[0][mf][nf], AH[mf], &blo[nf * 2]);
                            mma_f16(acc[0][mf][nf], AL[mf], &bh[nf * 2]);
                        }
                }
                // lat fragments -> outputs d1, d2
                ldsm_x4(AH[0], smu + 2 * A_TILE_B + aoff0 + kby);
                ldsm_x4(AH[1], smu + 2 * A_TILE_B + aoff1 + kby);
                ldsm_x4(AL[0], smu + 3 * A_TILE_B + aoff0 + kby);
                ldsm_x4(AL[1], smu + 3 * A_TILE_B + aoff1 + kby);
#pragma unroll
                for (int d = 1; d < 3; d++) {
                    uint32_t bb = smu + B_BASE_B + (uint32_t)(d * 2) * B_TILE_B;
                    ldsm_x4t(&bh[0],  bb + bcon + kbb);
                    ldsm_x4t(&bh[4],  bb + bcon + kbb + 32);
                    ldsm_x4t(&blo[0], bb + B_TILE_B + bcon + kbb);
                    ldsm_x4t(&blo[4], bb + B_TILE_B + bcon + kbb + 32);
#pragma unroll
                    for (int mf = 0; mf < 2; mf++)
#pragma unroll
                        for (int nf = 0; nf < 4; nf++) {
                            mma_f16(acc[d][mf][nf], AH[mf], &bh[nf * 2]);
                            mma_f16(acc[d][mf][nf], AH[mf], &blo[nf * 2]);
                            mma_f16(acc[d][mf][nf], AL[mf], &bh[nf * 2]);
                        }
                }
            }
        }

        // ---- epilogue: bias + sin + gate weight, register-resident
        int cb0 = n0c + wn * 32 + 2 * (lane & 3);
        float2 Bb[4], Bs[4], Bt2[4];
#pragma unroll
        for (int nf = 0; nf < 4; nf++) {
            Bb[nf]  = *(const float2*)(b  + (size_t)e * OUT_F + cb0 + nf * 8);
            Bs[nf]  = *(const float2*)(bl + (size_t)e * 2 * OUT_F + cb0 + nf * 8);
            Bt2[nf] = *(const float2*)(bl + (size_t)e * 2 * OUT_F + OUT_F + cb0 + nf * 8);
        }
#pragma unroll
        for (int mf = 0; mf < 2; mf++)
#pragma unroll
            for (int hh = 0; hh < 2; hh++) {
                int row = wm * 32 + mf * 16 + (lane >> 2) + 8 * hh;
                if (row < rows) {
                    int ent = s_ent[row];
                    int tok = ent & 0xFFFFFF, sl = (ent >> 24) & 1;
                    float wt = s_w[row];
                    float* gp = &g_part[sl][tok][0];
#pragma unroll
                    for (int nf = 0; nf < 4; nf++) {
                        float hv0 = acc[0][mf][nf][2 * hh + 0] + Bb[nf].x;
                        float hv1 = acc[0][mf][nf][2 * hh + 1] + Bb[nf].y;
                        float sc0 = acc[1][mf][nf][2 * hh + 0] + Bs[nf].x;
                        float sc1 = acc[1][mf][nf][2 * hh + 1] + Bs[nf].y;
                        float sh0 = acc[2][mf][nf][2 * hh + 0] + Bt2[nf].x;
                        float sh1 = acc[2][mf][nf][2 * hh + 1] + Bt2[nf].y;
                        float2 o;
                        o.x = wt * fast_sin(fmaf(OMEGA * hv0, sc0, sh0));
                        o.y = wt * fast_sin(fmaf(OMEGA * hv1, sc1, sh1));
                        *(float2*)(gp + cb0 + nf * 8) = o;
                    }
                }
            }
    }
}

// ---------------- kernel 3: combine slot contributions ----------------
__global__ void combine_kernel(float* __restrict__ out) {
    size_t i = (size_t)blockIdx.x * blockDim.x + threadIdx.x;
    const float4* p0 = (const float4*)&g_part[0][0][0];
    const float4* p1 = (const float4*)&g_part[1][0][0];
    float4 a = p0[i], c = p1[i];
    ((float4*)out)[i] = make_float4(a.x + c.x, a.y + c.y, a.z + c.z, a.w + c.w);
}

// ---------------- launch ----------------
extern "C" void kernel_launch(void* const* d_in, const int* in_sizes, int n_in,
                              void* d_out, int out_size) {
    const float* x   = (const float*)d_in[0];
    const float* lat = (const float*)d_in[1];
    const float* gw  = (const float*)d_in[2];
    const float* gb  = (const float*)d_in[3];
    const float* W   = (const float*)d_in[4];
    const float* b   = (const float*)d_in[5];
    const float* Wl  = (const float*)d_in[6];
    const float* bl  = (const float*)d_in[7];
    float* out = (float*)d_out;

    cudaFuncSetAttribute(expert_kernel,
                         cudaFuncAttributeMaxDynamicSharedMemorySize, SMEM_BYTES);

    init_kernel<<<1, 32>>>();
    gate_kernel<<<N_TOK / 8, 256>>>(x, gw, gb);
    cudaMemcpyAsync(out + (size_t)N_TOK * OUT_F, lat,
                    (size_t)N_TOK * IN_F * sizeof(float),
                    cudaMemcpyDeviceToDevice);
    expert_kernel<<<dim3(N_TOK / TM, NEXP), TH, SMEM_BYTES>>>(x, lat, W, b, Wl, bl);
    combine_kernel<<<(N_TOK * OUT_F / 4) / 256, 256>>>(out);
}